// round 13
// baseline (speedup 1.0000x reference)
#include <cuda_runtime.h>

#define TILE 64
#define NTHREADS 128
#define WARPS 4
#define ROWS_PER_WARP 16
#define PI_F 3.14159265358979323846f
#define RSQRT2 0.70710678118654752440f

// ---------- dots: 8 rows, accumulate partials into v[32] ----------
__device__ __forceinline__ void dots8(const float4* __restrict__ xr0,
                                      const float (*wsm)[1024],
                                      int lane, float* v)
{
    #pragma unroll
    for (int it = 0; it < 8; it++) {
        const int idx = it * 32 + lane;
        float4 w0 = ((const float4*)wsm[0])[idx];
        float4 w1 = ((const float4*)wsm[1])[idx];
        float4 w2 = ((const float4*)wsm[2])[idx];
        float4 w3 = ((const float4*)wsm[3])[idx];
        #pragma unroll
        for (int r = 0; r < 8; r++) {
            float4 xv = __ldcs(&xr0[(size_t)r * 256 + idx]);
            v[r*4+0] += xv.x*w0.x + xv.y*w0.y + xv.z*w0.z + xv.w*w0.w;
            v[r*4+1] += xv.x*w1.x + xv.y*w1.y + xv.z*w1.z + xv.w*w1.w;
            v[r*4+2] += xv.x*w2.x + xv.y*w2.y + xv.z*w2.z + xv.w*w2.w;
            v[r*4+3] += xv.x*w3.x + xv.y*w3.y + xv.z*w3.z + xv.w*w3.w;
        }
    }
}

// ---------- distributing reduce: 31 shfls; lane l ends with S[l] ----------
__device__ __forceinline__ float reduce32(int lane, float* v)
{
    const unsigned FULL = 0xffffffffu;
    #pragma unroll
    for (int i = 0; i < 16; i++) {
        float send = (lane & 16) ? v[i] : v[i+16];
        float recv = __shfl_xor_sync(FULL, send, 16);
        v[i] = ((lane & 16) ? v[i+16] : v[i]) + recv;
    }
    #pragma unroll
    for (int i = 0; i < 8; i++) {
        float send = (lane & 8) ? v[i] : v[i+8];
        float recv = __shfl_xor_sync(FULL, send, 8);
        v[i] = ((lane & 8) ? v[i+8] : v[i]) + recv;
    }
    #pragma unroll
    for (int i = 0; i < 4; i++) {
        float send = (lane & 4) ? v[i] : v[i+4];
        float recv = __shfl_xor_sync(FULL, send, 4);
        v[i] = ((lane & 4) ? v[i+4] : v[i]) + recv;
    }
    #pragma unroll
    for (int i = 0; i < 2; i++) {
        float send = (lane & 2) ? v[i] : v[i+2];
        float recv = __shfl_xor_sync(FULL, send, 2);
        v[i] = ((lane & 2) ? v[i+2] : v[i]) + recv;
    }
    {
        float send = (lane & 1) ? v[0] : v[1];
        float recv = __shfl_xor_sync(FULL, send, 1);
        v[0] = ((lane & 1) ? v[1] : v[0]) + recv;
    }
    return v[0];   // lane l: S for row l>>2, qubit l&3
}

// ---------- circuit: lanes 0..7 simulate rows lr0..lr0+7, write zsm ------
__device__ __forceinline__ void circuit8(float S, int lane, int lr0,
                                         const float (*usm)[8],
                                         const float* prebias,
                                         float4* zsm)
{
    const unsigned FULL = 0xffffffffu;
    // gather h[q] for this lane's row: S values sit on lanes 4*lane+q
    float h0 = __shfl_sync(FULL, S, (lane << 2) + 0);
    float h1 = __shfl_sync(FULL, S, (lane << 2) + 1);
    float h2 = __shfl_sync(FULL, S, (lane << 2) + 2);
    float h3 = __shfl_sync(FULL, S, (lane << 2) + 3);
    if (lane < 8) {
        float hq[4];
        hq[0] = tanhf(h0 + prebias[0]) * PI_F;
        hq[1] = tanhf(h1 + prebias[1]) * PI_F;
        hq[2] = tanhf(h2 + prebias[2]) * PI_F;
        hq[3] = tanhf(h3 + prebias[3]) * PI_F;

        float vr[4][2], vi[4][2];
        #pragma unroll
        for (int qq = 0; qq < 4; qq++) {
            float f = hq[qq];
            float sa, ca; sincosf(0.5f * atanf(f), &sa, &ca);
            float A  = (ca - sa) * RSQRT2;
            float Bv = (ca + sa) * RSQRT2;
            float sb, cb; sincosf(0.5f * atanf(f * f), &sb, &cb);
            vr[qq][0] = A  * cb;  vi[qq][0] = -A  * sb;
            vr[qq][1] = Bv * cb;  vi[qq][1] =  Bv * sb;
        }
        float c2r[4], c2i[4];
        #pragma unroll
        for (int j = 0; j < 4; j++) {
            int b3 = (j >> 1) & 1, b2 = j & 1;
            c2r[j] = vr[0][b3]*vr[1][b2] - vi[0][b3]*vi[1][b2];
            c2i[j] = vr[0][b3]*vi[1][b2] + vi[0][b3]*vr[1][b2];
        }
        float c3r[8], c3i[8];
        #pragma unroll
        for (int j = 0; j < 8; j++) {
            int hi = j >> 1, b1 = j & 1;
            c3r[j] = c2r[hi]*vr[2][b1] - c2i[hi]*vi[2][b1];
            c3i[j] = c2r[hi]*vi[2][b1] + c2i[hi]*vr[2][b1];
        }
        float pr[16], pim[16];
        #pragma unroll
        for (int j = 0; j < 16; j++) {
            int hi = j >> 1, b0 = j & 1;
            pr[j]  = c3r[hi]*vr[3][b0] - c3i[hi]*vi[3][b0];
            pim[j] = c3r[hi]*vi[3][b0] + c3i[hi]*vr[3][b0];
        }
        float tr[16], ti[16];
        #pragma unroll
        for (int j = 0; j < 16; j++) {
            int xg = j;
            xg ^= (xg & 1) << 3;
            xg ^= (xg >> 1) & 1;
            xg ^= ((xg >> 2) & 1) << 1;
            xg ^= ((xg >> 3) & 1) << 2;
            tr[j] = pr[xg];
            ti[j] = pim[xg];
        }
        #pragma unroll
        for (int qq = 0; qq < 4; qq++) {
            const float u00r = usm[qq][0], u00i = usm[qq][1];
            const float u01r = usm[qq][2], u01i = usm[qq][3];
            const float u10r = usm[qq][4], u10i = usm[qq][5];
            const float u11r = usm[qq][6], u11i = usm[qq][7];
            const int mask = 8 >> qq;
            #pragma unroll
            for (int j0 = 0; j0 < 16; j0++) {
                if (j0 & mask) continue;
                const int j1 = j0 | mask;
                float ar = tr[j0], ai = ti[j0];
                float br = tr[j1], bi = ti[j1];
                tr[j0] = u00r*ar - u00i*ai + u01r*br - u01i*bi;
                ti[j0] = u00r*ai + u00i*ar + u01r*bi + u01i*br;
                tr[j1] = u10r*ar - u10i*ai + u11r*br - u11i*bi;
                ti[j1] = u10r*ai + u10i*ar + u11r*bi + u11i*br;
            }
        }
        float z0 = 0.f, z1 = 0.f, z2 = 0.f, z3 = 0.f;
        #pragma unroll
        for (int j = 0; j < 16; j++) {
            float p = tr[j]*tr[j] + ti[j]*ti[j];
            z0 += (j & 8) ? -p : p;
            z1 += (j & 4) ? -p : p;
            z2 += (j & 2) ? -p : p;
            z3 += (j & 1) ? -p : p;
        }
        zsm[lr0 + lane] = make_float4(z0, z1, z2, z3);
    }
}

__global__ __launch_bounds__(NTHREADS, 7) void qp_kernel(
    const float* __restrict__ x,       // [B,1024]
    const float* __restrict__ pre_w,   // [4,1024]
    const float* __restrict__ pre_b,   // [4]
    const float* __restrict__ qw,      // [1,4,3]
    const float* __restrict__ post_w,  // [1024,4]
    const float* __restrict__ post_b,  // [1024]
    float* __restrict__ out,           // [B,1024]
    int B)
{
    __shared__ float wsm[4][1024];     // pre_w (16KB)
    __shared__ float4 zsm[TILE];       // expectations (1KB)
    __shared__ float usm[4][8];        // Rot matrices
    __shared__ float prebias[4];

    const int tid  = threadIdx.x;
    const int warp = tid >> 5;
    const int lane = tid & 31;
    const int tile0 = blockIdx.x * TILE;

    for (int i = tid; i < 4096; i += NTHREADS)
        ((float*)wsm)[i] = pre_w[i];
    if (tid < 4) {
        prebias[tid] = pre_b[tid];
        float phi = qw[tid * 3 + 0];
        float th  = qw[tid * 3 + 1];
        float om  = qw[tid * 3 + 2];
        float spo, cpo, spm, cpm, st, ct;
        sincosf(0.5f * (phi + om), &spo, &cpo);
        sincosf(0.5f * (phi - om), &spm, &cpm);
        sincosf(0.5f * th,         &st,  &ct);
        usm[tid][0] =  cpo * ct;  usm[tid][1] = -spo * ct;  // u00
        usm[tid][2] = -cpm * st;  usm[tid][3] = -spm * st;  // u01
        usm[tid][4] =  cpm * st;  usm[tid][5] = -spm * st;  // u10
        usm[tid][6] =  cpo * ct;  usm[tid][7] =  spo * ct;  // u11
    }
    __syncthreads();

    const int lr0g0 = warp * ROWS_PER_WARP;        // rows 0..7 of this warp
    const int lr0g1 = lr0g0 + 8;                   // rows 8..15
    const int r0g0 = tile0 + lr0g0;
    const int r0g1 = tile0 + lr0g1;
    const bool ok0 = (r0g0 + 7 < B);
    const bool ok1 = (r0g1 + 7 < B);

    const float4* pwg4 = (const float4*)post_w;    // pwg4[j] = post_w[j][0..3]
    const float4* pbg4 = (const float4*)post_b;

    // ---------- stage 1: dots + circuit for g0 ----------
    if (ok0) {
        float v[32];
        #pragma unroll
        for (int i = 0; i < 32; i++) v[i] = 0.0f;
        dots8((const float4*)(x + (size_t)r0g0 * 1024), wsm, lane, v);
        float S = reduce32(lane, v);
        circuit8(S, lane, lr0g0, usm, prebias, zsm);
    }
    __syncwarp();

    // ---------- stage 2: FUSED — g1 loads+dots interleaved with g0 stores
    float v1[32];
    #pragma unroll
    for (int i = 0; i < 32; i++) v1[i] = 0.0f;
    {
        const float4* xr1 = (const float4*)(x + (size_t)r0g1 * 1024);
        float4* o0 = (float4*)(out + (size_t)r0g0 * 1024);
        #pragma unroll
        for (int it = 0; it < 8; it++) {
            const int idx = it * 32 + lane;
            // --- g1 read side ---
            if (ok1) {
                float4 w0 = ((const float4*)wsm[0])[idx];
                float4 w1 = ((const float4*)wsm[1])[idx];
                float4 w2 = ((const float4*)wsm[2])[idx];
                float4 w3 = ((const float4*)wsm[3])[idx];
                #pragma unroll
                for (int r = 0; r < 8; r++) {
                    float4 xv = __ldcs(&xr1[(size_t)r * 256 + idx]);
                    v1[r*4+0] += xv.x*w0.x + xv.y*w0.y + xv.z*w0.z + xv.w*w0.w;
                    v1[r*4+1] += xv.x*w1.x + xv.y*w1.y + xv.z*w1.z + xv.w*w1.w;
                    v1[r*4+2] += xv.x*w2.x + xv.y*w2.y + xv.z*w2.z + xv.w*w2.w;
                    v1[r*4+3] += xv.x*w3.x + xv.y*w3.y + xv.z*w3.z + xv.w*w3.w;
                }
            }
            // --- g0 write side ---
            if (ok0) {
                float4 ga0 = __ldg(&pwg4[4*idx + 0]);
                float4 ga1 = __ldg(&pwg4[4*idx + 1]);
                float4 ga2 = __ldg(&pwg4[4*idx + 2]);
                float4 ga3 = __ldg(&pwg4[4*idx + 3]);
                float4 bb  = __ldg(&pbg4[idx]);
                #pragma unroll
                for (int r = 0; r < 8; r++) {
                    float4 zv = zsm[lr0g0 + r];
                    float4 o;
                    o.x = bb.x + zv.x*ga0.x + zv.y*ga0.y + zv.z*ga0.z + zv.w*ga0.w;
                    o.y = bb.y + zv.x*ga1.x + zv.y*ga1.y + zv.z*ga1.z + zv.w*ga1.w;
                    o.z = bb.z + zv.x*ga2.x + zv.y*ga2.y + zv.z*ga2.z + zv.w*ga2.w;
                    o.w = bb.w + zv.x*ga3.x + zv.y*ga3.y + zv.z*ga3.z + zv.w*ga3.w;
                    __stcs(&o0[(size_t)r * 256 + idx], o);
                }
            }
        }
    }

    // ---------- stage 3: reduce + circuit for g1, tail stores ----------
    if (ok1) {
        float S = reduce32(lane, v1);
        circuit8(S, lane, lr0g1, usm, prebias, zsm);
    }
    __syncwarp();

    if (ok1) {
        float4* o1 = (float4*)(out + (size_t)r0g1 * 1024);
        #pragma unroll
        for (int jt = 0; jt < 8; jt++) {
            const int idx = jt * 32 + lane;
            float4 ga0 = __ldg(&pwg4[4*idx + 0]);
            float4 ga1 = __ldg(&pwg4[4*idx + 1]);
            float4 ga2 = __ldg(&pwg4[4*idx + 2]);
            float4 ga3 = __ldg(&pwg4[4*idx + 3]);
            float4 bb  = __ldg(&pbg4[idx]);
            #pragma unroll
            for (int r = 0; r < 8; r++) {
                float4 zv = zsm[lr0g1 + r];
                float4 o;
                o.x = bb.x + zv.x*ga0.x + zv.y*ga0.y + zv.z*ga0.z + zv.w*ga0.w;
                o.y = bb.y + zv.x*ga1.x + zv.y*ga1.y + zv.z*ga1.z + zv.w*ga1.w;
                o.z = bb.z + zv.x*ga2.x + zv.y*ga2.y + zv.z*ga2.z + zv.w*ga2.w;
                o.w = bb.w + zv.x*ga3.x + zv.y*ga3.y + zv.z*ga3.z + zv.w*ga3.w;
                __stcs(&o1[(size_t)r * 256 + idx], o);
            }
        }
    }
}

extern "C" void kernel_launch(void* const* d_in, const int* in_sizes, int n_in,
                              void* d_out, int out_size) {
    const float* x      = (const float*)d_in[0];
    const float* pre_w  = (const float*)d_in[1];
    const float* pre_b  = (const float*)d_in[2];
    const float* qw     = (const float*)d_in[3];
    const float* post_w = (const float*)d_in[4];
    const float* post_b = (const float*)d_in[5];
    float* out = (float*)d_out;

    const int B = in_sizes[0] / 1024;
    const int blocks = (B + TILE - 1) / TILE;
    qp_kernel<<<blocks, NTHREADS>>>(x, pre_w, pre_b, qw, post_w, post_b, out, B);
}